// round 1
// baseline (speedup 1.0000x reference)
#include <cuda_runtime.h>

// Problem constants (fixed by the dataset)
#define BB 2
#define SS 2048
#define DD 1024
#define HH 16
#define DK 64
#define MM (BB * SS)  // 4096 rows

// Scratch (allocation-free rule: __device__ globals)
__device__ float g_q[(size_t)BB * HH * SS * DK];    // (B,H,S,DK)
__device__ float g_k[(size_t)BB * HH * SS * DK];
__device__ float g_v[(size_t)BB * HH * SS * DK];
__device__ float g_ctx[(size_t)BB * SS * DD];       // (B,S,D)

// ---------------------------------------------------------------------------
// Tiled SGEMM core: C[M,N] = A[M,K] * W[N,K]^T + bias
// BM=BN=128, BK=8, 8x8 microtile, 256 threads.
// SCATTER: write to (B,H,S,DK) layout; else plain row-major (M,N).
// ---------------------------------------------------------------------------
template <bool SCATTER>
__device__ __forceinline__ void gemm128(const float* __restrict__ A,
                                        const float* __restrict__ W,
                                        const float* __restrict__ bias,
                                        float* __restrict__ out) {
    constexpr int K = DD;  // 1024
    __shared__ float As[8][128];
    __shared__ float Ws[8][128];

    const int tid = threadIdx.x;
    const int m0 = blockIdx.y * 128;
    const int n0 = blockIdx.x * 128;

    const int lr = tid >> 1;          // 0..127 load row
    const int lc = (tid & 1) * 4;     // 0 or 4 (k offset)
    const int tr = (tid >> 4) * 8;    // microtile row
    const int tc = (tid & 15) * 8;    // microtile col

    float acc[8][8];
#pragma unroll
    for (int i = 0; i < 8; i++)
#pragma unroll
        for (int j = 0; j < 8; j++) acc[i][j] = 0.0f;

    const float* Ap = A + (size_t)(m0 + lr) * K + lc;
    const float* Wp = W + (size_t)(n0 + lr) * K + lc;

    for (int k0 = 0; k0 < K; k0 += 8) {
        float4 a = *(const float4*)(Ap + k0);
        float4 w = *(const float4*)(Wp + k0);
        As[lc + 0][lr] = a.x; As[lc + 1][lr] = a.y;
        As[lc + 2][lr] = a.z; As[lc + 3][lr] = a.w;
        Ws[lc + 0][lr] = w.x; Ws[lc + 1][lr] = w.y;
        Ws[lc + 2][lr] = w.z; Ws[lc + 3][lr] = w.w;
        __syncthreads();

#pragma unroll
        for (int kk = 0; kk < 8; kk++) {
            float ra[8], rb[8];
#pragma unroll
            for (int i = 0; i < 8; i++) ra[i] = As[kk][tr + i];
#pragma unroll
            for (int j = 0; j < 8; j++) rb[j] = Ws[kk][tc + j];
#pragma unroll
            for (int i = 0; i < 8; i++)
#pragma unroll
                for (int j = 0; j < 8; j++) acc[i][j] += ra[i] * rb[j];
        }
        __syncthreads();
    }

#pragma unroll
    for (int i = 0; i < 8; i++) {
        const int m = m0 + tr + i;
#pragma unroll
        for (int j = 0; j < 8; j++) {
            const int n = n0 + tc + j;
            const float c = acc[i][j] + bias[n];
            if (SCATTER) {
                const int b = m >> 11;        // m / S
                const int s = m & 2047;       // m % S
                const int h = n >> 6;         // n / DK
                const int d = n & 63;         // n % DK
                out[(((size_t)(b * HH + h)) * SS + s) * DK + d] = c;
            } else {
                out[(size_t)m * DD + n] = c;
            }
        }
    }
}

__global__ void __launch_bounds__(256) qkv_kernel(
    const float* __restrict__ x,
    const float* __restrict__ Wq, const float* __restrict__ bq,
    const float* __restrict__ Wk, const float* __restrict__ bk,
    const float* __restrict__ Wv, const float* __restrict__ bv) {
    const int z = blockIdx.z;
    const float* W = (z == 0) ? Wq : (z == 1) ? Wk : Wv;
    const float* bias = (z == 0) ? bq : (z == 1) ? bk : bv;
    float* out = (z == 0) ? g_q : (z == 1) ? g_k : g_v;
    gemm128<true>(x, W, bias, out);
}

__global__ void __launch_bounds__(256) oproj_kernel(
    const float* __restrict__ Wo, const float* __restrict__ bo,
    float* __restrict__ out) {
    gemm128<false>(g_ctx, Wo, bo, out);
}

// ---------------------------------------------------------------------------
// Flash-style attention. One thread per query row (128 q rows / block).
// q row + O accumulator in registers; K/V 64-row tiles in smem (broadcast
// float4 reads). Lazy-max online softmax: O rescaled only on new row-max.
// ---------------------------------------------------------------------------
__global__ void __launch_bounds__(128) attn_kernel(const int* __restrict__ mask) {
    __shared__ float ks[64 * 64];
    __shared__ float vs[64 * 64];
    __shared__ int msk[64];

    const int t = threadIdx.x;
    const int bh = blockIdx.y;
    const int b = bh >> 4;     // / H
    const int h = bh & 15;     // % H
    const int qs = blockIdx.x * 128 + t;

    const float* qp = g_q + ((size_t)bh * SS + qs) * DK;
    float q[64];
#pragma unroll
    for (int i = 0; i < 16; i++) {
        float4 v4 = ((const float4*)qp)[i];
        q[4 * i + 0] = v4.x; q[4 * i + 1] = v4.y;
        q[4 * i + 2] = v4.z; q[4 * i + 3] = v4.w;
    }

    float O[64];
#pragma unroll
    for (int d = 0; d < 64; d++) O[d] = 0.0f;
    float mrow = -1e30f;
    float l = 0.0f;

    const float* kbase = g_k + (size_t)bh * SS * DK;
    const float* vbase = g_v + (size_t)bh * SS * DK;

    for (int kt = 0; kt < SS / 64; kt++) {
        __syncthreads();
        const float4* ksrc = (const float4*)(kbase + (size_t)kt * 64 * 64);
        const float4* vsrc = (const float4*)(vbase + (size_t)kt * 64 * 64);
#pragma unroll
        for (int i = 0; i < 8; i++) {
            ((float4*)ks)[t + i * 128] = ksrc[t + i * 128];
            ((float4*)vs)[t + i * 128] = vsrc[t + i * 128];
        }
        if (t < 64) msk[t] = mask[b * SS + kt * 64 + t];
        __syncthreads();

#pragma unroll 1
        for (int j = 0; j < 64; j++) {
            const float4* kj = (const float4*)(ks + j * 64);
            float s = 0.0f;
#pragma unroll
            for (int d4 = 0; d4 < 16; d4++) {
                float4 kk = kj[d4];
                s += q[4 * d4 + 0] * kk.x + q[4 * d4 + 1] * kk.y +
                     q[4 * d4 + 2] * kk.z + q[4 * d4 + 3] * kk.w;
            }
            s *= 0.125f;  // 1/sqrt(64)
            if (msk[j] == 0) s = -1e9f;

            if (s > mrow) {
                const float corr = __expf(mrow - s);
                l *= corr;
#pragma unroll
                for (int d = 0; d < 64; d++) O[d] *= corr;
                mrow = s;
            }
            const float p = __expf(s - mrow);
            l += p;

            const float4* vj = (const float4*)(vs + j * 64);
#pragma unroll
            for (int d4 = 0; d4 < 16; d4++) {
                float4 vv = vj[d4];
                O[4 * d4 + 0] += p * vv.x;
                O[4 * d4 + 1] += p * vv.y;
                O[4 * d4 + 2] += p * vv.z;
                O[4 * d4 + 3] += p * vv.w;
            }
        }
    }

    const float inv = 1.0f / l;
    float* op = g_ctx + ((size_t)(b * SS + qs)) * DD + h * DK;
#pragma unroll
    for (int i = 0; i < 16; i++) {
        float4 o4;
        o4.x = O[4 * i + 0] * inv;
        o4.y = O[4 * i + 1] * inv;
        o4.z = O[4 * i + 2] * inv;
        o4.w = O[4 * i + 3] * inv;
        ((float4*)op)[i] = o4;
    }
}

// ---------------------------------------------------------------------------
// Inputs (metadata order): x, mask, Wq, bq, Wk, bk, Wv, bv, Wo, bo
// ---------------------------------------------------------------------------
extern "C" void kernel_launch(void* const* d_in, const int* in_sizes, int n_in,
                              void* d_out, int out_size) {
    const float* x  = (const float*)d_in[0];
    const int*   mk = (const int*)d_in[1];
    const float* Wq = (const float*)d_in[2];
    const float* bq = (const float*)d_in[3];
    const float* Wk = (const float*)d_in[4];
    const float* bk = (const float*)d_in[5];
    const float* Wv = (const float*)d_in[6];
    const float* bv = (const float*)d_in[7];
    const float* Wo = (const float*)d_in[8];
    const float* bo = (const float*)d_in[9];
    float* out = (float*)d_out;

    // QKV projections: C(4096,1024) = x * W^T + b, scattered to (B,H,S,DK)
    qkv_kernel<<<dim3(DD / 128, MM / 128, 3), 256>>>(x, Wq, bq, Wk, bk, Wv, bv);

    // Attention: 16 q-blocks of 128 rows x 32 (b,h) pairs
    attn_kernel<<<dim3(SS / 128, BB * HH), 128>>>(mk);

    // Output projection -> d_out
    oproj_kernel<<<dim3(DD / 128, MM / 128), 256>>>(Wo, bo, out);
}